// round 4
// baseline (speedup 1.0000x reference)
#include <cuda_runtime.h>
#include <cuda_bf16.h>
#include <cstdint>

// SimpleAttention via mma.sync (HMMA bf16, base sm_100 ISA):
// y = softmax((XWq+bq)(XWk+bk)^T/32)(XWv+bv) Wh + bh
// B=4, S=2048, H=1024. fp32 in/out; GEMMs via bf16 hi/lo split, 3-term MMA.
// R4: 3-stage cp.async pipeline in GEMM; softmax fused with P hi/lo split.

#define B_   4
#define S_   2048
#define H_   1024
#define MTOT (B_ * S_)   // 8192

// ------------------------------- scratch -----------------------------------
__device__ __align__(256) __nv_bfloat16 g_Xhi[(size_t)MTOT * H_];
__device__ __align__(256) __nv_bfloat16 g_Xlo[(size_t)MTOT * H_];
__device__ __align__(256) __nv_bfloat16 g_Qhi[(size_t)MTOT * H_];
__device__ __align__(256) __nv_bfloat16 g_Qlo[(size_t)MTOT * H_];
__device__ __align__(256) __nv_bfloat16 g_Khi[(size_t)MTOT * H_];
__device__ __align__(256) __nv_bfloat16 g_Klo[(size_t)MTOT * H_];
__device__ __align__(256) float         g_Vf [(size_t)MTOT * H_];
__device__ __align__(256) __nv_bfloat16 g_VThi[(size_t)MTOT * H_];  // [b][1024][2048]
__device__ __align__(256) __nv_bfloat16 g_VTlo[(size_t)MTOT * H_];
__device__ __align__(256) float         g_Sf [(size_t)B_ * S_ * S_];
__device__ __align__(256) __nv_bfloat16 g_Phi[(size_t)B_ * S_ * S_];
__device__ __align__(256) __nv_bfloat16 g_Plo[(size_t)B_ * S_ * S_];
__device__ __align__(256) __nv_bfloat16 g_Chi[(size_t)MTOT * H_];
__device__ __align__(256) __nv_bfloat16 g_Clo[(size_t)MTOT * H_];
__device__ __align__(256) __nv_bfloat16 g_WqThi[(size_t)H_ * H_];
__device__ __align__(256) __nv_bfloat16 g_WqTlo[(size_t)H_ * H_];
__device__ __align__(256) __nv_bfloat16 g_WkThi[(size_t)H_ * H_];
__device__ __align__(256) __nv_bfloat16 g_WkTlo[(size_t)H_ * H_];
__device__ __align__(256) __nv_bfloat16 g_WvThi[(size_t)H_ * H_];
__device__ __align__(256) __nv_bfloat16 g_WvTlo[(size_t)H_ * H_];
__device__ __align__(256) __nv_bfloat16 g_WhThi[(size_t)H_ * H_];
__device__ __align__(256) __nv_bfloat16 g_WhTlo[(size_t)H_ * H_];

// --------------------------- PTX helpers -----------------------------------
__device__ __forceinline__ uint32_t smem_u32(const void* p) {
    uint32_t a;
    asm("{ .reg .u64 t; cvta.to.shared.u64 t, %1; cvt.u32.u64 %0, t; }" : "=r"(a) : "l"(p));
    return a;
}
__device__ __forceinline__ void cp16(uint32_t dst, const void* src) {
    asm volatile("cp.async.cg.shared.global [%0], [%1], 16;" :: "r"(dst), "l"(src));
}
#define CP_COMMIT() asm volatile("cp.async.commit_group;" ::: "memory")
#define CP_WAIT(n)  asm volatile("cp.async.wait_group %0;" :: "n"(n) : "memory")

__device__ __forceinline__ void ldm4(uint32_t* r, uint32_t addr) {
    asm volatile("ldmatrix.sync.aligned.m8n8.x4.shared.b16 {%0,%1,%2,%3}, [%4];"
                 : "=r"(r[0]), "=r"(r[1]), "=r"(r[2]), "=r"(r[3]) : "r"(addr));
}
__device__ __forceinline__ void mma16816(float* d, const uint32_t* a, const uint32_t* b) {
    asm volatile("mma.sync.aligned.m16n8k16.row.col.f32.bf16.bf16.f32 "
                 "{%0,%1,%2,%3}, {%4,%5,%6,%7}, {%8,%9}, {%0,%1,%2,%3};"
                 : "+f"(d[0]), "+f"(d[1]), "+f"(d[2]), "+f"(d[3])
                 : "r"(a[0]), "r"(a[1]), "r"(a[2]), "r"(a[3]), "r"(b[0]), "r"(b[1]));
}

// --------------------------- bf16 mma GEMM ---------------------------------
// C[M,N] = alpha * A[M,K] @ B[N,K]^T + bias[N], via hi/lo bf16 split (3 terms)
// EPI 0: fp32 out. EPI 1: split bf16 hi/lo out.
static constexpr int KC     = 32;           // K per chunk (bf16 elems)
static constexpr int ROWB   = 80;           // bytes per smem row (64 data + 16 pad)
static constexpr int TILE_B = 128 * ROWB;   // 10240
static constexpr int STAGE  = 4 * TILE_B;   // Ahi, Alo, Bhi, Blo = 40960
static constexpr int NSTG   = 3;
static constexpr uint32_t SMEM_BYTES = NSTG * STAGE;  // 122880

template <int EPI, bool HAS_BIAS>
__global__ __launch_bounds__(256)
void gemm_mma(const __nv_bfloat16* __restrict__ Ahi, const __nv_bfloat16* __restrict__ Alo,
              const __nv_bfloat16* __restrict__ Bhi, const __nv_bfloat16* __restrict__ Blo,
              const float* __restrict__ bias,
              float* __restrict__ outF, __nv_bfloat16* __restrict__ outHi,
              __nv_bfloat16* __restrict__ outLo,
              int M, int N, int K, float alpha, size_t sA, size_t sB, size_t sC)
{
    extern __shared__ char smem[];
    const int tid = threadIdx.x;
    const int wid = tid >> 5;
    const int lane = tid & 31;

    Ahi += (size_t)blockIdx.z * sA; Alo += (size_t)blockIdx.z * sA;
    Bhi += (size_t)blockIdx.z * sB; Blo += (size_t)blockIdx.z * sB;
    float* outFb = outF; __nv_bfloat16 *outHib = outHi, *outLob = outLo;
    if (EPI == 0) outFb += (size_t)blockIdx.z * sC;
    else { outHib += (size_t)blockIdx.z * sC; outLob += (size_t)blockIdx.z * sC; }

    const int rowBase = blockIdx.y * 128;
    const int colBase = blockIdx.x * 128;
    const uint32_t sb = smem_u32(smem);

    // ---- async stage loader: 4 tiles x 128 rows x 64B; 2 cp16 per thread/tile
    auto ld_stage = [&](int t, int s) {
        const uint32_t base = sb + (uint32_t)s * STAGE;
        const int koff = t * KC;
        const int idx0 = tid * 2;
#pragma unroll
        for (int i = 0; i < 2; i++) {
            const int idx = idx0 + i;            // 0..511
            const int row = idx >> 2, ch = idx & 3;
            const uint32_t so = row * ROWB + ch * 16;
            const size_t ga = (size_t)(rowBase + row) * K + koff + ch * 8;
            const size_t gb = (size_t)(colBase + row) * K + koff + ch * 8;
            cp16(base + 0 * TILE_B + so, Ahi + ga);
            cp16(base + 1 * TILE_B + so, Alo + ga);
            cp16(base + 2 * TILE_B + so, Bhi + gb);
            cp16(base + 3 * TILE_B + so, Blo + gb);
        }
        CP_COMMIT();
    };

    // warp tiling: 4 (M) x 2 (N) warps; warp tile 32x64
    const int wm = (wid >> 1) * 32;
    const int wn = (wid & 1) * 64;

    // ldmatrix lane address components
    const int aRow = wm + (lane & 7) + ((lane >> 3) & 1) * 8;   // + mt*16
    const int aK8  = (lane >> 4) * 8;
    const int bRow = wn + ((lane >> 4) & 1) * 8 + (lane & 7);   // + p*16
    const int bK8  = ((lane >> 3) & 1) * 8;

    float acc[2][8][4];
#pragma unroll
    for (int mt = 0; mt < 2; mt++)
#pragma unroll
        for (int nt = 0; nt < 8; nt++)
#pragma unroll
            for (int q = 0; q < 4; q++) acc[mt][nt][q] = 0.0f;

    const int T = K / KC;

    // prologue: fill NSTG-1 stages
    ld_stage(0, 0);
    ld_stage(1, 1);

    int stage = 0;
    for (int t = 0; t < T; t++) {
        // wait for stage t's data (allow 1 group -- stage t+1 -- in flight)
        if (t + 1 < T) { CP_WAIT(1); } else { CP_WAIT(0); }
        __syncthreads();

        // issue loads for t+2 into the stage freed at iteration t-1
        if (t + 2 < T) ld_stage(t + 2, (stage + 2) % NSTG);

        const uint32_t base = sb + (uint32_t)stage * STAGE;
#pragma unroll
        for (int kk = 0; kk < 2; kk++) {
            const int k0 = kk * 16;
            uint32_t a_hi[2][4], a_lo[2][4], b_hi[4][4], b_lo[4][4];
#pragma unroll
            for (int mt = 0; mt < 2; mt++) {
                uint32_t ad = base + (uint32_t)((aRow + mt * 16) * ROWB + (k0 + aK8) * 2);
                ldm4(a_hi[mt], ad);
                ldm4(a_lo[mt], ad + TILE_B);
            }
#pragma unroll
            for (int p = 0; p < 4; p++) {
                uint32_t bd = base + 2 * TILE_B +
                              (uint32_t)((bRow + p * 16) * ROWB + (k0 + bK8) * 2);
                ldm4(b_hi[p], bd);
                ldm4(b_lo[p], bd + TILE_B);
            }
#pragma unroll
            for (int mt = 0; mt < 2; mt++)
#pragma unroll
                for (int nt = 0; nt < 8; nt++) {
                    const uint32_t* bh = &b_hi[nt >> 1][(nt & 1) * 2];
                    const uint32_t* bl = &b_lo[nt >> 1][(nt & 1) * 2];
                    mma16816(acc[mt][nt], a_hi[mt], bh);
                    mma16816(acc[mt][nt], a_hi[mt], bl);
                    mma16816(acc[mt][nt], a_lo[mt], bh);
                }
        }
        stage = (stage + 1) % NSTG;
    }

    // ---- epilogue from registers
#pragma unroll
    for (int mt = 0; mt < 2; mt++) {
        const int r0 = rowBase + wm + mt * 16 + (lane >> 2);
#pragma unroll
        for (int nt = 0; nt < 8; nt++) {
            const int col = colBase + wn + nt * 8 + (lane & 3) * 2;
            float bx = 0.f, by = 0.f;
            if (HAS_BIAS) { bx = bias[col]; by = bias[col + 1]; }
#pragma unroll
            for (int half = 0; half < 2; half++) {
                const int r = r0 + half * 8;
                float f0 = acc[mt][nt][half * 2 + 0] * alpha + bx;
                float f1 = acc[mt][nt][half * 2 + 1] * alpha + by;
                if (EPI == 0) {
                    *reinterpret_cast<float2*>(&outFb[(size_t)r * N + col]) =
                        make_float2(f0, f1);
                } else {
                    __nv_bfloat16 h0 = __float2bfloat16_rn(f0);
                    __nv_bfloat16 h1 = __float2bfloat16_rn(f1);
                    __nv_bfloat16 l0 = __float2bfloat16_rn(f0 - __bfloat162float(h0));
                    __nv_bfloat16 l1 = __float2bfloat16_rn(f1 - __bfloat162float(h1));
                    __nv_bfloat162 hv; hv.x = h0; hv.y = h1;
                    __nv_bfloat162 lv; lv.x = l0; lv.y = l1;
                    *reinterpret_cast<__nv_bfloat162*>(&outHib[(size_t)r * N + col]) = hv;
                    *reinterpret_cast<__nv_bfloat162*>(&outLob[(size_t)r * N + col]) = lv;
                }
            }
        }
    }
}

// --------------------------- aux kernels -----------------------------------
__global__ void split_f32(const float* __restrict__ in, __nv_bfloat16* __restrict__ hi,
                          __nv_bfloat16* __restrict__ lo, size_t n4)
{
    size_t i = (size_t)blockIdx.x * blockDim.x + threadIdx.x;
    if (i >= n4) return;
    float4 v = reinterpret_cast<const float4*>(in)[i];
    float f[4] = {v.x, v.y, v.z, v.w};
    __nv_bfloat16 h[4], l[4];
#pragma unroll
    for (int j = 0; j < 4; j++) {
        h[j] = __float2bfloat16_rn(f[j]);
        l[j] = __float2bfloat16_rn(f[j] - __bfloat162float(h[j]));
    }
    __nv_bfloat162 h0; h0.x = h[0]; h0.y = h[1];
    __nv_bfloat162 h1; h1.x = h[2]; h1.y = h[3];
    __nv_bfloat162 l0; l0.x = l[0]; l0.y = l[1];
    __nv_bfloat162 l1; l1.x = l[2]; l1.y = l[3];
    reinterpret_cast<__nv_bfloat162*>(hi)[i * 2 + 0] = h0;
    reinterpret_cast<__nv_bfloat162*>(hi)[i * 2 + 1] = h1;
    reinterpret_cast<__nv_bfloat162*>(lo)[i * 2 + 0] = l0;
    reinterpret_cast<__nv_bfloat162*>(lo)[i * 2 + 1] = l1;
}

__global__ void transpose_split(const float* __restrict__ in, __nv_bfloat16* __restrict__ ohi,
                                __nv_bfloat16* __restrict__ olo, int R, int C)
{
    __shared__ float tile[32][33];
    in  += (size_t)blockIdx.z * R * C;
    ohi += (size_t)blockIdx.z * R * C;
    olo += (size_t)blockIdx.z * R * C;
    const int rb = blockIdx.y * 32, cb = blockIdx.x * 32;
    const int tx = threadIdx.x, ty = threadIdx.y;
#pragma unroll
    for (int i = ty; i < 32; i += 8)
        tile[i][tx] = in[(size_t)(rb + i) * C + cb + tx];
    __syncthreads();
#pragma unroll
    for (int i = ty; i < 32; i += 8) {
        float f = tile[tx][i];
        __nv_bfloat16 h = __float2bfloat16_rn(f);
        __nv_bfloat16 l = __float2bfloat16_rn(f - __bfloat162float(h));
        ohi[(size_t)(cb + i) * R + rb + tx] = h;
        olo[(size_t)(cb + i) * R + rb + tx] = l;
    }
}

// softmax over rows of Sf [rows of 2048 fp32], writing split bf16 probs directly.
__global__ void softmax_split(const float* __restrict__ Sm,
                              __nv_bfloat16* __restrict__ Phi,
                              __nv_bfloat16* __restrict__ Plo)
{
    const int row = blockIdx.x;
    const int tid = threadIdx.x;
    const int lane = tid & 31, warp = tid >> 5;
    const float4* p = reinterpret_cast<const float4*>(Sm + (size_t)row * S_);
    float4 v0 = p[tid], v1 = p[tid + 256];
    __shared__ float rM[8], rS[8];
    float m = fmaxf(fmaxf(fmaxf(v0.x, v0.y), fmaxf(v0.z, v0.w)),
                    fmaxf(fmaxf(v1.x, v1.y), fmaxf(v1.z, v1.w)));
#pragma unroll
    for (int o = 16; o > 0; o >>= 1) m = fmaxf(m, __shfl_xor_sync(~0u, m, o));
    if (lane == 0) rM[warp] = m;
    __syncthreads();
    float mA = rM[0];
#pragma unroll
    for (int w = 1; w < 8; w++) mA = fmaxf(mA, rM[w]);
    v0.x = __expf(v0.x - mA); v0.y = __expf(v0.y - mA);
    v0.z = __expf(v0.z - mA); v0.w = __expf(v0.w - mA);
    v1.x = __expf(v1.x - mA); v1.y = __expf(v1.y - mA);
    v1.z = __expf(v1.z - mA); v1.w = __expf(v1.w - mA);
    float s = (v0.x + v0.y) + (v0.z + v0.w) + (v1.x + v1.y) + (v1.z + v1.w);
#pragma unroll
    for (int o = 16; o > 0; o >>= 1) s += __shfl_xor_sync(~0u, s, o);
    if (lane == 0) rS[warp] = s;
    __syncthreads();
    float sA = 0.f;
#pragma unroll
    for (int w = 0; w < 8; w++) sA += rS[w];
    const float inv = 1.0f / sA;

    float f[8] = {v0.x * inv, v0.y * inv, v0.z * inv, v0.w * inv,
                  v1.x * inv, v1.y * inv, v1.z * inv, v1.w * inv};
    __nv_bfloat16 h[8], l[8];
#pragma unroll
    for (int j = 0; j < 8; j++) {
        h[j] = __float2bfloat16_rn(f[j]);
        l[j] = __float2bfloat16_rn(f[j] - __bfloat162float(h[j]));
    }
    __nv_bfloat162* ph = reinterpret_cast<__nv_bfloat162*>(Phi + (size_t)row * S_);
    __nv_bfloat162* pl = reinterpret_cast<__nv_bfloat162*>(Plo + (size_t)row * S_);
#pragma unroll
    for (int j = 0; j < 2; j++) {
        __nv_bfloat162 a; a.x = h[j * 2]; a.y = h[j * 2 + 1];
        __nv_bfloat162 b; b.x = l[j * 2]; b.y = l[j * 2 + 1];
        ph[tid * 2 + j] = a;
        pl[tid * 2 + j] = b;
    }
#pragma unroll
    for (int j = 0; j < 2; j++) {
        __nv_bfloat162 a; a.x = h[4 + j * 2]; a.y = h[4 + j * 2 + 1];
        __nv_bfloat162 b; b.x = l[4 + j * 2]; b.y = l[4 + j * 2 + 1];
        ph[(tid + 256) * 2 + j] = a;
        pl[(tid + 256) * 2 + j] = b;
    }
}

// ------------------------------- launch ------------------------------------
extern "C" void kernel_launch(void* const* d_in, const int* in_sizes, int n_in,
                              void* d_out, int out_size)
{
    const float* X  = (const float*)d_in[0];
    const float* Wq = (const float*)d_in[1];
    const float* bq = (const float*)d_in[2];
    const float* Wk = (const float*)d_in[3];
    const float* bk = (const float*)d_in[4];
    const float* Wv = (const float*)d_in[5];
    const float* bv = (const float*)d_in[6];
    const float* Wh = (const float*)d_in[7];
    const float* bh = (const float*)d_in[8];
    float* out = (float*)d_out;

    cudaFuncSetAttribute(gemm_mma<0, true>,  cudaFuncAttributeMaxDynamicSharedMemorySize, SMEM_BYTES);
    cudaFuncSetAttribute(gemm_mma<0, false>, cudaFuncAttributeMaxDynamicSharedMemorySize, SMEM_BYTES);
    cudaFuncSetAttribute(gemm_mma<1, true>,  cudaFuncAttributeMaxDynamicSharedMemorySize, SMEM_BYTES);
    cudaFuncSetAttribute(gemm_mma<1, false>, cudaFuncAttributeMaxDynamicSharedMemorySize, SMEM_BYTES);

    __nv_bfloat16 *Xhi, *Xlo, *Qhi, *Qlo, *Khi, *Klo, *VThi, *VTlo;
    __nv_bfloat16 *Phi, *Plo, *Chi, *Clo;
    __nv_bfloat16 *WqThi, *WqTlo, *WkThi, *WkTlo, *WvThi, *WvTlo, *WhThi, *WhTlo;
    float *Vf, *Sf;
    cudaGetSymbolAddress((void**)&Xhi, g_Xhi);   cudaGetSymbolAddress((void**)&Xlo, g_Xlo);
    cudaGetSymbolAddress((void**)&Qhi, g_Qhi);   cudaGetSymbolAddress((void**)&Qlo, g_Qlo);
    cudaGetSymbolAddress((void**)&Khi, g_Khi);   cudaGetSymbolAddress((void**)&Klo, g_Klo);
    cudaGetSymbolAddress((void**)&Vf,  g_Vf);
    cudaGetSymbolAddress((void**)&VThi, g_VThi); cudaGetSymbolAddress((void**)&VTlo, g_VTlo);
    cudaGetSymbolAddress((void**)&Sf,  g_Sf);
    cudaGetSymbolAddress((void**)&Phi, g_Phi);   cudaGetSymbolAddress((void**)&Plo, g_Plo);
    cudaGetSymbolAddress((void**)&Chi, g_Chi);   cudaGetSymbolAddress((void**)&Clo, g_Clo);
    cudaGetSymbolAddress((void**)&WqThi, g_WqThi); cudaGetSymbolAddress((void**)&WqTlo, g_WqTlo);
    cudaGetSymbolAddress((void**)&WkThi, g_WkThi); cudaGetSymbolAddress((void**)&WkTlo, g_WkTlo);
    cudaGetSymbolAddress((void**)&WvThi, g_WvThi); cudaGetSymbolAddress((void**)&WvTlo, g_WvTlo);
    cudaGetSymbolAddress((void**)&WhThi, g_WhThi); cudaGetSymbolAddress((void**)&WhTlo, g_WhTlo);

    // 1) split X; transpose+split weights
    {
        size_t n4 = (size_t)MTOT * H_ / 4;
        split_f32<<<(unsigned)((n4 + 255) / 256), 256>>>(X, Xhi, Xlo, n4);
        dim3 tb(32, 8), tg(H_ / 32, H_ / 32, 1);
        transpose_split<<<tg, tb>>>(Wq, WqThi, WqTlo, H_, H_);
        transpose_split<<<tg, tb>>>(Wk, WkThi, WkTlo, H_, H_);
        transpose_split<<<tg, tb>>>(Wv, WvThi, WvTlo, H_, H_);
        transpose_split<<<tg, tb>>>(Wh, WhThi, WhTlo, H_, H_);
    }

    // 2) projections
    {
        dim3 grid(H_ / 128, MTOT / 128, 1);
        gemm_mma<1, true><<<grid, 256, SMEM_BYTES>>>(Xhi, Xlo, WqThi, WqTlo, bq,
            nullptr, Qhi, Qlo, MTOT, H_, H_, 1.0f, 0, 0, 0);
        gemm_mma<1, true><<<grid, 256, SMEM_BYTES>>>(Xhi, Xlo, WkThi, WkTlo, bk,
            nullptr, Khi, Klo, MTOT, H_, H_, 1.0f, 0, 0, 0);
        gemm_mma<0, true><<<grid, 256, SMEM_BYTES>>>(Xhi, Xlo, WvThi, WvTlo, bv,
            Vf, nullptr, nullptr, MTOT, H_, H_, 1.0f, 0, 0, 0);
    }

    // 3) V^T split (per batch: [2048,1024] -> [1024,2048])
    {
        dim3 tb(32, 8), tg(H_ / 32, S_ / 32, B_);
        transpose_split<<<tg, tb>>>(Vf, VThi, VTlo, S_, H_);
    }

    // 4) scores = Q @ K^T / 32
    {
        dim3 grid(S_ / 128, S_ / 128, B_);
        gemm_mma<0, false><<<grid, 256, SMEM_BYTES>>>(Qhi, Qlo, Khi, Klo, nullptr,
            Sf, nullptr, nullptr, S_, S_, H_, 0.03125f,
            (size_t)S_ * H_, (size_t)S_ * H_, (size_t)S_ * S_);
    }

    // 5) softmax fused with split P
    softmax_split<<<B_ * S_, 256>>>(Sf, Phi, Plo);

    // 6) context = P @ V  (B operand = V^T [1024,2048])
    {
        dim3 grid(H_ / 128, S_ / 128, B_);
        gemm_mma<1, false><<<grid, 256, SMEM_BYTES>>>(Phi, Plo, VThi, VTlo, nullptr,
            nullptr, Chi, Clo, S_, H_, S_, 1.0f,
            (size_t)S_ * S_, (size_t)S_ * H_, (size_t)S_ * H_);
    }

    // 7) out = C @ Wh + bh
    {
        dim3 grid(H_ / 128, MTOT / 128, 1);
        gemm_mma<0, true><<<grid, 256, SMEM_BYTES>>>(Chi, Clo, WhThi, WhTlo, bh,
            out, nullptr, nullptr, MTOT, H_, H_, 1.0f, 0, 0, 0);
    }
}